// round 16
// baseline (speedup 1.0000x reference)
#include <cuda_runtime.h>

#define BB 4
#define NN 8192
#define G 32
#define G3 (G * G * G)
#define CAP 16
#define GL 5.0f
#define CS (2.0f * GL / (float)G)       // 0.3125 cell size
#define CS2 (CS * CS)
#define R3B (9.0f * CS2)                // (3*CS)^2 certification bound
#define MAXSPILL 8192
#define PREP_THREADS 64
#define PREP_BLOCKS (BB * NN / 4 / PREP_THREADS)
#define ZERO_TOTAL (2 * BB * G3)        // 262144
#define NQ (2 * BB * NN)                // 65536 total queries
#define Q2BLOCKS 128

// Device-global scratch (no allocations allowed)
__device__ float4 g_flat[2][BB][NN];            // [0]=clean, [1]=predp
__device__ int    g_cnt [2][BB][G3];            // per-cell counts (1 MB)
__device__ float4 g_cell[2][BB][G3][CAP];       // per-cell points (67 MB, L2-resident hot set)
__device__ float4 g_spill[2][BB][MAXSPILL];     // overflow points (exact; ~empty at CAP=16)
__device__ int    g_spillcnt[2][BB];
__device__ int    g_nv[BB];
__device__ float  g_l1sum;
__device__ float  g_cd;
__device__ int    g_work_idx[NQ];
__device__ float  g_work_best[NQ];
__device__ int    g_nwork;
__device__ int    g_ticket;

__global__ void zero_kernel() {
    int idx = blockIdx.x * blockDim.x + threadIdx.x;   // covers ZERO_TOTAL exactly
    ((int*)g_cnt)[idx] = 0;
    if (idx < 8)  ((int*)g_spillcnt)[idx] = 0;
    if (idx < BB) g_nv[idx] = 0;
    if (idx == 0) { g_l1sum = 0.0f; g_cd = 0.0f; g_nwork = 0; g_ticket = 0; }
}

__device__ __forceinline__ int cell_of(float x, float y, float z) {
    int cx = min(max((int)floorf((x + GL) * (1.0f / CS)), 0), G - 1);
    int cy = min(max((int)floorf((y + GL) * (1.0f / CS)), 0), G - 1);
    int cz = min(max((int)floorf((z + GL) * (1.0f / CS)), 0), G - 1);
    return (cz * G + cy) * G + cx;
}

__device__ __forceinline__ void grid_insert(int s, int b, float x, float y, float z) {
    int cell = cell_of(x, y, z);
    int k = atomicAdd(&g_cnt[s][b][cell], 1);
    if (k < CAP) {
        g_cell[s][b][cell][k] = make_float4(x, y, z, 0.0f);
    } else {
        int j = atomicAdd(&g_spillcnt[s][b], 1);
        if (j < MAXSPILL) g_spill[s][b][j] = make_float4(x, y, z, 0.0f);
    }
}

__global__ void __launch_bounds__(PREP_THREADS)
prep_kernel(const float* __restrict__ pred,
            const float* __restrict__ target,
            const int*   __restrict__ mask,
            const float* __restrict__ points) {
    int gid = blockIdx.x * PREP_THREADS + threadIdx.x;   // 0..8191, 4 points each
    int b = gid >> 11;

    const float4* P4 = (const float4*)(pred   + (size_t)gid * 12);
    const float4* T4 = (const float4*)(target + (size_t)gid * 12);
    const float4* X4 = (const float4*)(points + (size_t)gid * 12);
    float4 pA = P4[0], pB = P4[1], pC = P4[2];
    float4 tA = T4[0], tB = T4[1], tC = T4[2];
    float4 xA = X4[0], xB = X4[1], xC = X4[2];
    int4 mm = *(const int4*)(mask + (size_t)gid * 4);

    float px[4] = {pA.x, pA.w, pB.z, pC.y};
    float py[4] = {pA.y, pB.x, pB.w, pC.z};
    float pz[4] = {pA.z, pB.y, pC.x, pC.w};
    float tx[4] = {tA.x, tA.w, tB.z, tC.y};
    float ty[4] = {tA.y, tB.x, tB.w, tC.z};
    float tz[4] = {tA.z, tB.y, tC.x, tC.w};
    float xx[4] = {xA.x, xA.w, xB.z, xC.y};
    float xy[4] = {xA.y, xB.x, xB.w, xC.z};
    float xz[4] = {xA.z, xB.y, xC.x, xC.w};
    int   mk[4] = {mm.x, mm.y, mm.z, mm.w};

    int cnt = mk[0] + mk[1] + mk[2] + mk[3];
    int slot = (cnt > 0) ? atomicAdd(&g_nv[b], cnt) : 0;

    float li = 0.0f;
    #pragma unroll
    for (int k = 0; k < 4; k++) {
        if (mk[k]) {
            li += (fabsf(px[k] - tx[k]) + fabsf(py[k] - ty[k]) + fabsf(pz[k] - tz[k]))
                  * (1.0f / 3.0f);
            float c0 = xx[k] + tx[k], c1 = xy[k] + ty[k], c2 = xz[k] + tz[k];   // clean
            float q0 = xx[k] + px[k], q1 = xy[k] + py[k], q2 = xz[k] + pz[k];   // predp
            g_flat[0][b][slot] = make_float4(c0, c1, c2, 0.0f);
            g_flat[1][b][slot] = make_float4(q0, q1, q2, 0.0f);
            grid_insert(0, b, c0, c1, c2);   // set0 = clean grid
            grid_insert(1, b, q0, q1, q2);   // set1 = predp grid
            slot++;
        }
    }

    #pragma unroll
    for (int o = 16; o; o >>= 1) li += __shfl_down_sync(0xFFFFFFFFu, li, o);
    if ((threadIdx.x & 31) == 0) atomicAdd(&g_l1sum, li);
}

__device__ __forceinline__ void scan_cell(int s, int b, int cell,
                                          float qx, float qy, float qz, float& best) {
    int n = min(g_cnt[s][b][cell], CAP);
    const float4* p = g_cell[s][b][cell];
    for (int k = 0; k < n; k++) {
        float4 t = p[k];
        float dx = qx - t.x, dy = qy - t.y, dz = qz - t.z;
        float d2 = fmaf(dx, dx, fmaf(dy, dy, dz * dz));
        best = fminf(best, d2);
    }
}

// Phase 1: count-preload + slot-major 27-cell scan (MLP-flat); certified ->
// accumulate, else -> worklist.
__global__ void __launch_bounds__(256)
query1_kernel() {
    __shared__ float red[8];
    int idx = blockIdx.x * 256 + threadIdx.x;   // covers NQ exactly
    int dir = idx >> 15;                        // block-uniform
    int r   = idx & 32767;
    int b   = r >> 13;                          // block-uniform
    int i   = r & (NN - 1);
    int nv  = g_nv[b];
    int s   = 1 - dir;

    float acc = 0.0f;
    if (i < nv) {
        float4 q = g_flat[dir][b][i];
        float qx = q.x, qy = q.y, qz = q.z;
        int cx = min(max((int)floorf((qx + GL) * (1.0f / CS)), 0), G - 1);
        int cy = min(max((int)floorf((qy + GL) * (1.0f / CS)), 0), G - 1);
        int cz = min(max((int)floorf((qz + GL) * (1.0f / CS)), 0), G - 1);

        float best = 1e30f;

        // spill points (exact; ~empty with CAP=16)
        int sc = min(g_spillcnt[s][b], MAXSPILL);
        for (int k = 0; k < sc; k++) {
            float4 t = g_spill[s][b][k];
            float dx = qx - t.x, dy = qy - t.y, dz = qz - t.z;
            best = fminf(best, fmaf(dx, dx, fmaf(dy, dy, dz * dz)));
        }

        // preload all 27 cell counts: one latency epoch, MLP 27
        int cnts[27], coff[27];
        #pragma unroll
        for (int t = 0; t < 27; t++) {
            int dzz = t / 9 - 1, dyy = (t / 3) % 3 - 1, dxx = t % 3 - 1;
            int x = cx + dxx, y = cy + dyy, z = cz + dzz;
            bool ok = ((unsigned)x < G) & ((unsigned)y < G) & ((unsigned)z < G);
            int cell = (z * G + y) * G + x;
            coff[t] = cell;
            cnts[t] = ok ? min(g_cnt[s][b][cell], CAP) : 0;
        }
        int mx = 0;
        #pragma unroll
        for (int t = 0; t < 27; t++) mx = max(mx, cnts[t]);

        // slot-major scan: per j all live cells probed (independent loads)
        const float4* cellbase = &g_cell[s][b][0][0];
        for (int j = 0; j < mx; j++) {
            #pragma unroll
            for (int t = 0; t < 27; t++) {
                if (j < cnts[t]) {
                    float4 p = cellbase[coff[t] * CAP + j];
                    float dx = qx - p.x, dy = qy - p.y, dz = qz - p.z;
                    best = fminf(best, fmaf(dx, dx, fmaf(dy, dy, dz * dz)));
                }
            }
        }

        if (best <= CS2) {
            acc = best;                          // certified exact
        } else {
            int j = atomicAdd(&g_nwork, 1);      // defer to phase 2
            g_work_idx[j] = idx;
            g_work_best[j] = best;
        }
    }

    // block reduction -> one scaled atomic (b uniform per block)
    #pragma unroll
    for (int o = 16; o; o >>= 1) acc += __shfl_down_sync(0xFFFFFFFFu, acc, o);
    if ((threadIdx.x & 31) == 0) red[threadIdx.x >> 5] = acc;
    __syncthreads();
    if (threadIdx.x == 0 && nv > 0) {
        float bs = red[0] + red[1] + red[2] + red[3]
                 + red[4] + red[5] + red[6] + red[7];
        atomicAdd(&g_cd, bs / (float)nv);
    }
}

// Phase 2: one WARP per worklist item. Lane-parallel radius-3 cube scan;
// if still uncertified, exact warp brute-force over all db points.
__global__ void __launch_bounds__(256)
query2_kernel(float* __restrict__ out) {
    int nw = min(g_nwork, NQ);
    int lane = threadIdx.x & 31;
    int gwarp = (blockIdx.x * 256 + threadIdx.x) >> 5;
    const int nwarps = Q2BLOCKS * 8;

    for (int item = gwarp; item < nw; item += nwarps) {
        int idx = g_work_idx[item];
        int dir = idx >> 15;
        int r   = idx & 32767;
        int b   = r >> 13;
        int i   = r & (NN - 1);
        int s   = 1 - dir;
        int nvb = g_nv[b];
        float4 q = g_flat[dir][b][i];
        float qx = q.x, qy = q.y, qz = q.z;
        int cx = min(max((int)floorf((qx + GL) * (1.0f / CS)), 0), G - 1);
        int cy = min(max((int)floorf((qy + GL) * (1.0f / CS)), 0), G - 1);
        int cz = min(max((int)floorf((qz + GL) * (1.0f / CS)), 0), G - 1);

        // lane-parallel cube radius 3 (skip the cheby<=1 cells phase 1 did)
        float lb = 1e30f;
        for (int t = lane; t < 343; t += 32) {
            int dz = t / 49 - 3;
            int rem = t % 49;
            int dy = rem / 7 - 3;
            int dx = rem % 7 - 3;
            int ch = max(abs(dx), max(abs(dy), abs(dz)));
            if (ch <= 1) continue;
            int x = cx + dx, y = cy + dy, z = cz + dz;
            if ((unsigned)x >= G || (unsigned)y >= G || (unsigned)z >= G) continue;
            scan_cell(s, b, (z * G + y) * G + x, qx, qy, qz, lb);
        }
        #pragma unroll
        for (int o = 16; o; o >>= 1) lb = fminf(lb, __shfl_xor_sync(0xFFFFFFFFu, lb, o));
        float best = fminf(g_work_best[item], lb);

        if (best > R3B) {
            // exact warp brute-force over the whole db set (coalesced)
            const float4* P = g_flat[s][b];
            float bb = 1e30f;
            for (int k = lane; k < nvb; k += 32) {
                float4 t = P[k];
                float dx = qx - t.x, dy = qy - t.y, dz = qz - t.z;
                bb = fminf(bb, fmaf(dx, dx, fmaf(dy, dy, dz * dz)));
            }
            #pragma unroll
            for (int o = 16; o; o >>= 1) bb = fminf(bb, __shfl_xor_sync(0xFFFFFFFFu, bb, o));
            best = fminf(best, bb);
        }

        if (lane == 0) atomicAdd(&g_cd, best / (float)nvb);
    }

    // finalize via ticket: last arriving block writes the scalar
    __syncthreads();
    if (threadIdx.x == 0) {
        __threadfence();
        int ticket = atomicAdd(&g_ticket, 1);
        if (ticket == Q2BLOCKS - 1) {
            int cnt = g_nv[0] + g_nv[1] + g_nv[2] + g_nv[3];
            float l1 = *((volatile float*)&g_l1sum) / (float)max(cnt, 1);
            float cd = *((volatile float*)&g_cd) / (float)BB;
            out[0] = 0.5f * (l1 + cd);
        }
    }
}

extern "C" void kernel_launch(void* const* d_in, const int* in_sizes, int n_in,
                              void* d_out, int out_size) {
    const float* pred   = (const float*)d_in[0];
    const float* target = (const float*)d_in[1];
    const int*   mask   = (const int*)d_in[2];
    const float* points = (const float*)d_in[3];

    zero_kernel<<<ZERO_TOTAL / 256, 256>>>();
    prep_kernel<<<PREP_BLOCKS, PREP_THREADS>>>(pred, target, mask, points);
    query1_kernel<<<NQ / 256, 256>>>();
    query2_kernel<<<Q2BLOCKS, 256>>>((float*)d_out);
}

// round 17
// speedup vs baseline: 1.6498x; 1.6498x over previous
#include <cuda_runtime.h>

#define BB 4
#define NN 8192
#define PAIRS (NN / 2)
#define THREADS 256
#define UQ 8            // queries per thread -> 2048 queries per q-block
#define QBLOCKS 4       // worst-case coverage 4*2048 = 8192 queries
#define MSLICES 32      // 2 dirs * 4 b * 2 active qtiles * 32 = 512 jobs (R9-proven count)
#define CHUNKP 512      // db pairs staged in smem (16KB); len=64 fits one stage
#define FBLOCKS 64      // 64*256*4 = 65536 = 2*BB*NN, one float4/thread
#define PREP_THREADS 64
#define PREP_BLOCKS (BB * NN / 4 / PREP_THREADS)   // 8192 threads, 4 pts each

// Scratch (device globals: no allocations allowed; BSS zero-init on first call,
// finalize's last block resets counters for subsequent graph replays)
__device__ float4 g_q [2][BB][NN];         // query points (x,y,z,|.|^2)
__device__ float  g_db2[2][BB][PAIRS][8];  // pair-interleaved db: [x0x1][y0y1][z0z1][w0w1]
__device__ float  g_minbuf[2][BB][NN];     // per-query clamped min (qw+e, >=0)
__device__ int    g_nv[BB];
__device__ float  g_l1sum;
__device__ float  g_cd;
__device__ int    g_ticket;

__device__ __forceinline__ unsigned long long pack2(float v) {
    unsigned long long r;
    asm("mov.b64 %0, {%1, %1};" : "=l"(r) : "f"(v));
    return r;
}

__device__ __forceinline__ unsigned long long fma2(unsigned long long a,
                                                   unsigned long long b,
                                                   unsigned long long c) {
    unsigned long long d;
    asm("fma.rn.f32x2 %0, %1, %2, %3;" : "=l"(d) : "l"(a), "l"(b), "l"(c));
    return d;
}

__global__ void __launch_bounds__(PREP_THREADS)
prep_kernel(const float* __restrict__ pred,
            const float* __restrict__ target,
            const int*   __restrict__ mask,
            const float* __restrict__ points) {
    int gid = blockIdx.x * PREP_THREADS + threadIdx.x;   // 0..8191, 4 points each

    // init minbuf to +inf (index-based, no interaction with slot atomics)
    float4 inf4 = make_float4(__int_as_float(0x7F800000), __int_as_float(0x7F800000),
                              __int_as_float(0x7F800000), __int_as_float(0x7F800000));
    ((float4*)g_minbuf)[gid * 2 + 0] = inf4;
    ((float4*)g_minbuf)[gid * 2 + 1] = inf4;

    int b = gid >> 11;                                   // 2048 threads per batch

    // wide loads: 4 points = 12 floats = 3 float4 from each tensor
    const float4* P4 = (const float4*)(pred   + (size_t)gid * 12);
    const float4* T4 = (const float4*)(target + (size_t)gid * 12);
    const float4* X4 = (const float4*)(points + (size_t)gid * 12);
    float4 pA = P4[0], pB = P4[1], pC = P4[2];
    float4 tA = T4[0], tB = T4[1], tC = T4[2];
    float4 xA = X4[0], xB = X4[1], xC = X4[2];
    int4 mm = *(const int4*)(mask + (size_t)gid * 4);

    float px[4] = {pA.x, pA.w, pB.z, pC.y};
    float py[4] = {pA.y, pB.x, pB.w, pC.z};
    float pz[4] = {pA.z, pB.y, pC.x, pC.w};
    float tx[4] = {tA.x, tA.w, tB.z, tC.y};
    float ty[4] = {tA.y, tB.x, tB.w, tC.z};
    float tz[4] = {tA.z, tB.y, tC.x, tC.w};
    float xx[4] = {xA.x, xA.w, xB.z, xC.y};
    float xy[4] = {xA.y, xB.x, xB.w, xC.z};
    float xz[4] = {xA.z, xB.y, xC.x, xC.w};
    int   mk[4] = {mm.x, mm.y, mm.z, mm.w};

    int cnt = mk[0] + mk[1] + mk[2] + mk[3];
    int slot = (cnt > 0) ? atomicAdd(&g_nv[b], cnt) : 0;

    float li = 0.0f;
    #pragma unroll
    for (int k = 0; k < 4; k++) {
        if (mk[k]) {
            li += (fabsf(px[k] - tx[k]) + fabsf(py[k] - ty[k]) + fabsf(pz[k] - tz[k]))
                  * (1.0f / 3.0f);
            float c0 = xx[k] + tx[k], c1 = xy[k] + ty[k], c2 = xz[k] + tz[k];   // clean
            float q0 = xx[k] + px[k], q1 = xy[k] + py[k], q2 = xz[k] + pz[k];   // predp
            float cn = fmaf(c0, c0, fmaf(c1, c1, c2 * c2));
            float pn = fmaf(q0, q0, fmaf(q1, q1, q2 * q2));
            g_q[0][b][slot] = make_float4(c0, c1, c2, cn);
            g_q[1][b][slot] = make_float4(q0, q1, q2, pn);
            int pi = slot >> 1, h = slot & 1;
            // dir 0: queries=clean, db=pred points (store -2*p, |p|^2)
            float* d0 = &g_db2[0][b][pi][0];
            d0[0 + h] = -2.0f * q0; d0[2 + h] = -2.0f * q1;
            d0[4 + h] = -2.0f * q2; d0[6 + h] = pn;
            // dir 1: queries=pred, db=clean points
            float* d1 = &g_db2[1][b][pi][0];
            d1[0 + h] = -2.0f * c0; d1[2 + h] = -2.0f * c1;
            d1[4 + h] = -2.0f * c2; d1[6 + h] = cn;
            slot++;
        }
    }

    #pragma unroll
    for (int o = 16; o; o >>= 1) li += __shfl_down_sync(0xFFFFFFFFu, li, o);
    if ((threadIdx.x & 31) == 0) atomicAdd(&g_l1sum, li);
}

__global__ void __launch_bounds__(THREADS, 2)
pair_kernel() {
    int z = blockIdx.z;
    int dir = z & 1;
    int b = z >> 1;
    int nv = g_nv[b];
    int qbase = blockIdx.x * (THREADS * UQ);
    if (qbase >= nv) return;                          // block-uniform
    int nvp = (nv + 1) >> 1;                          // padded pair count
    int len = (nvp + MSLICES - 1) / MSLICES;
    int m0 = blockIdx.y * len;
    int m1 = min(m0 + len, nvp);
    if (m0 >= m1) return;                             // block-uniform
    bool oddnv = (nv & 1) != 0;
    int padidx = 2 * (nvp - 1) + 1;                   // float4 index of (z0,z1,w0,w1) of last pair

    __shared__ float4 sdb[2 * CHUNKP];

    const float4* __restrict__ Q  = g_q[dir][b];
    const float4* __restrict__ DB = (const float4*)&g_db2[dir][b][0][0];

    unsigned long long qx2[UQ], qy2[UQ], qz2[UQ];
    float qw[UQ], mnl[UQ], mnh[UQ];
    #pragma unroll
    for (int u = 0; u < UQ; u++) {
        int qi = min(qbase + u * THREADS + (int)threadIdx.x, nv - 1);
        float4 q = Q[qi];
        qx2[u] = pack2(q.x); qy2[u] = pack2(q.y); qz2[u] = pack2(q.z);
        qw[u] = q.w;
        mnl[u] = 3.4e38f; mnh[u] = 3.4e38f;
    }

    for (int mc = m0; mc < m1; mc += CHUNKP) {
        int cnt = min(CHUNKP, m1 - mc);
        __syncthreads();
        for (int t = threadIdx.x; t < cnt * 2; t += THREADS) {
            float4 v = DB[2 * mc + t];
            // patch the pad half of the last pair when nv is odd (stale slot)
            if (oddnv && (2 * mc + t) == padidx) v.w = 1e30f;
            sdb[t] = v;
        }
        __syncthreads();
        #pragma unroll 2
        for (int j = 0; j < cnt; j++) {
            ulonglong2 xy = *(const ulonglong2*)(sdb + 2 * j);      // x0x1 | y0y1
            ulonglong2 zw = *(const ulonglong2*)(sdb + 2 * j + 1);  // z0z1 | w0w1
            #pragma unroll
            for (int u = 0; u < UQ; u++) {
                // e2 = {w + (-2p).q} for both db halves at once
                unsigned long long acc = fma2(zw.x, qz2[u], zw.y);
                acc = fma2(xy.y, qy2[u], acc);
                acc = fma2(xy.x, qx2[u], acc);
                float elo, ehi;
                asm("mov.b64 {%0, %1}, %2;" : "=f"(elo), "=f"(ehi) : "l"(acc));
                mnl[u] = fminf(mnl[u], elo);
                mnh[u] = fminf(mnh[u], ehi);
            }
        }
    }

    #pragma unroll
    for (int u = 0; u < UQ; u++) {
        int qi = qbase + u * THREADS + (int)threadIdx.x;
        if (qi < nv) {
            // fold query norm + clamp (both monotone, commute past cross-block min)
            float val = fmaxf(qw[u] + fminf(mnl[u], mnh[u]), 0.0f);
            atomicMin((int*)&g_minbuf[dir][b][qi], __float_as_int(val)); // val >= 0
        }
    }
}

__global__ void __launch_bounds__(256)
finalize_kernel(float* __restrict__ out) {
    __shared__ float red[8];
    int tid = threadIdx.x;
    int idx4 = (blockIdx.x * 256 + tid) * 4;          // FBLOCKS*256*4 == 2*BB*NN exactly
    int b = (idx4 >> 13) & (BB - 1);
    int i = idx4 & (NN - 1);
    int nv = g_nv[b];
    float inv_nv = (nv > 0) ? (1.0f / (float)nv) : 0.0f;

    float4 v = *(const float4*)(((const float*)g_minbuf) + idx4);
    float s = 0.0f;
    if (i + 0 < nv) s += v.x;
    if (i + 1 < nv) s += v.y;
    if (i + 2 < nv) s += v.z;
    if (i + 3 < nv) s += v.w;
    float acc = s * inv_nv;

    #pragma unroll
    for (int o = 16; o; o >>= 1) acc += __shfl_down_sync(0xFFFFFFFFu, acc, o);
    if ((tid & 31) == 0) red[tid >> 5] = acc;
    __syncthreads();
    if (tid == 0) {
        float bs = red[0] + red[1] + red[2] + red[3] + red[4] + red[5] + red[6] + red[7];
        atomicAdd(&g_cd, bs);
        __threadfence();
        int ticket = atomicAdd(&g_ticket, 1);
        if (ticket == FBLOCKS - 1) {
            int cnt = g_nv[0] + g_nv[1] + g_nv[2] + g_nv[3];
            float l1 = *((volatile float*)&g_l1sum) / (float)max(cnt, 1);
            float cd = *((volatile float*)&g_cd) / (float)BB;
            out[0] = 0.5f * (l1 + cd);
            // reset for next graph replay (self-restoring launch)
            g_nv[0] = 0; g_nv[1] = 0; g_nv[2] = 0; g_nv[3] = 0;
            g_l1sum = 0.0f; g_cd = 0.0f; g_ticket = 0;
        }
    }
}

extern "C" void kernel_launch(void* const* d_in, const int* in_sizes, int n_in,
                              void* d_out, int out_size) {
    const float* pred   = (const float*)d_in[0];
    const float* target = (const float*)d_in[1];
    const int*   mask   = (const int*)d_in[2];
    const float* points = (const float*)d_in[3];

    prep_kernel<<<PREP_BLOCKS, PREP_THREADS>>>(pred, target, mask, points);
    pair_kernel<<<dim3(QBLOCKS, MSLICES, 2 * BB), THREADS>>>();
    finalize_kernel<<<FBLOCKS, 256>>>((float*)d_out);
}